// round 15
// baseline (speedup 1.0000x reference)
#include <cuda_runtime.h>
#include <math.h>

#define NCELL 512
#define C 32
#define NREP 32           // counter replicas per cell (replica = point_idx & 31)
#define CAP32 64          // slots per (cell, replica); mean ~30.5
#define SCAP 1280         // smem record capacity per bin; mean ~977, +9.7 sigma
#define KT_STAGE 27648    // 27*32*32 per conv stage

// -------- static scratch (no cudaMalloc allowed) --------
__device__ int   g_cnt32[NCELL * NREP];
__device__ int4  g_rec32[NCELL * NREP * CAP32];   // {idx, fx, fy, fz}
__device__ float g_img[NCELL * C];
__device__ float g_h1 [NCELL * C];
__device__ float g_t  [NCELL * C];
__device__ float g_out[NCELL * C];
__device__ float g_B  [NCELL * C];
__device__ float g_kt [3 * KT_STAGE];             // transposed kernels [stage][tap][i][o]

// -------- zero counters/buffers + transpose conv kernels to [tap][i][o] --------
__global__ void zero_k(const float* __restrict__ enc, const float* __restrict__ inn,
                       const float* __restrict__ dec) {
    int j = blockIdx.x * 256 + threadIdx.x;          // grid 384 -> 98304 threads
    if (j < NCELL * NREP) g_cnt32[j] = 0;
    if (j < NCELL * C) {
        g_img[j] = 0.f; g_h1[j] = 0.f; g_t[j] = 0.f; g_out[j] = 0.f;
    }
    if (j < KT_STAGE) {                               // one element per stage per thread
        int tap = j >> 10, rem = j & 1023;
        int i = rem >> 5, o = rem & 31;
        int src = (tap * 32 + o) * 32 + i;            // original [tap][o][i]
        g_kt[j]                = __ldg(&enc[src]);
        g_kt[KT_STAGE + j]     = __ldg(&inn[src]);
        g_kt[2 * KT_STAGE + j] = __ldg(&dec[src]);
    }
}

// -------- bin points (R8 measured-best config: 1 point/thread) --------
__global__ void bin_k(const float* __restrict__ pos, int N) {
    int p = blockIdx.x * 256 + threadIdx.x;
    if (p >= N) return;
    float sx = pos[3 * p + 0] * 8.f;
    float sy = pos[3 * p + 1] * 8.f;
    float sz = pos[3 * p + 2] * 8.f;
    float bx = floorf(sx), by = floorf(sy), bz = floorf(sz);
    int cell = ((((int)bx) & 7) << 6) | ((((int)by) & 7) << 3) | (((int)bz) & 7);
    int r = p & (NREP - 1);
    int slot = atomicAdd(&g_cnt32[cell * NREP + r], 1);
    if (slot < CAP32) {
        int4 rec;
        rec.x = p;
        rec.y = __float_as_int(sx - bx);
        rec.z = __float_as_int(sy - by);
        rec.w = __float_as_int(sz - bz);
        g_rec32[(cell * NREP + r) * CAP32 + slot] = rec;
    }
}

#define ACC(rc, fc) { \
    float fx = __int_as_float((rc).y), fy = __int_as_float((rc).z), fz = __int_as_float((rc).w); \
    float gx = 1.f - fx, gy = 1.f - fy, gz = 1.f - fz; \
    float w00 = gy * gz, w01 = gy * fz, w10 = fy * gz, w11 = fy * fz; \
    float p0 = gx * (fc), p1 = fx * (fc); \
    a0 += w00 * p0; a1 += w01 * p0; a2 += w10 * p0; a3 += w11 * p0; \
    a4 += w00 * p1; a5 += w01 * p1; a6 += w10 * p1; a7 += w11 * p1; }

// -------- scatter (R13 protected): 1 CTA/bin, 16 warps, padded smem records,
//          guard-free 4-deep feat prefetch, unroll-4 --------
__global__ void __launch_bounds__(512) scatter_k(const float* __restrict__ feat) {
    __shared__ int4  s_rec[SCAP + 64];
    __shared__ int   s_pref[NREP + 1];
    __shared__ float s_all[16][8][32];

    const int b    = blockIdx.x;
    const int w    = threadIdx.x >> 5;               // 0..15
    const int lane = threadIdx.x & 31;

    if (threadIdx.x < 32) {
        int c = g_cnt32[b * NREP + lane];
        if (c > CAP32) c = CAP32;
        int x = c;
        #pragma unroll
        for (int d = 1; d < 32; d <<= 1) {
            int y = __shfl_up_sync(0xffffffffu, x, d);
            if (lane >= d) x += y;
        }
        s_pref[lane + 1] = x;
        if (lane == 0) s_pref[0] = 0;
    }
    __syncthreads();

    #pragma unroll
    for (int r = w; r < NREP; r += 16) {
        int base = s_pref[r];
        int c    = s_pref[r + 1] - base;
        const int4* src = g_rec32 + (b * NREP + r) * CAP32;
        for (int t = lane; t < c; t += 32) {
            int d = base + t;
            if (d < SCAP) s_rec[d] = __ldg(src + t);
        }
    }
    {
        int Tt = s_pref[NREP]; if (Tt > SCAP) Tt = SCAP;
        if (threadIdx.x < 64) s_rec[Tt + threadIdx.x] = make_int4(0, 0, 0, 0);
    }
    __syncthreads();

    int T = s_pref[NREP];
    if (T > SCAP) T = SCAP;

    float a0=0,a1=0,a2=0,a3=0,a4=0,a5=0,a6=0,a7=0;
    float F[4];
    #pragma unroll
    for (int t = 0; t < 4; t++)
        F[t] = __ldg(feat + s_rec[w + t * 16].x * C + lane);

    int k = 0;
    #pragma unroll 4
    for (int j = w; j < T; j += 16, k++) {
        int t = k & 3;
        int4 rc = s_rec[j];
        float fc = F[t];
        F[t] = __ldg(feat + s_rec[j + 64].x * C + lane);
        ACC(rc, fc);
    }

    s_all[w][0][lane] = a0; s_all[w][1][lane] = a1;
    s_all[w][2][lane] = a2; s_all[w][3][lane] = a3;
    s_all[w][4][lane] = a4; s_all[w][5][lane] = a5;
    s_all[w][6][lane] = a6; s_all[w][7][lane] = a7;
    __syncthreads();

    int cn = w & 7;
    int qb = (w >> 3) * 8;
    float s = 0.f;
    #pragma unroll
    for (int q = 0; q < 8; q++) s += s_all[qb + q][cn][lane];
    int bx = b >> 6, by = (b >> 3) & 7, bz = b & 7;
    int cx = (bx + (cn >> 2)) & 7;
    int cy = (by + ((cn >> 1) & 1)) & 7;
    int cz = (bz + (cn & 1)) & 7;
    atomicAdd(&g_img[((cx << 6) | (cy << 3) | cz) * C + lane], s);
}

// -------- periodic 3x3x3 conv: grid = 9 (dx,dy) tap-groups x 16 half-slabs.
//          Each CTA stages one shifted 32-cell tile once and computes all 3 dz
//          taps from it via z-rotated smem reads. 512 threads, 2 cells/warp. --------
// stage 0: img->h1; stage 1: h1->t; stage 2: decoder with fused h1+silu(t) staging
__global__ void __launch_bounds__(512) conv_k(int stage) {
    const float* src = (stage == 0) ? g_img : g_h1;
    float*       dst = (stage == 0) ? g_h1  : (stage == 1) ? g_t : g_out;
    const float* kern = g_kt + stage * KT_STAGE;

    __shared__ float s_in[32 * 32];
    const int tid = threadIdx.x;
    const int o = tid & 31, w = tid >> 5;             // 16 warps
    const int tg  = blockIdx.x % 9;                   // (dx,dy) group
    const int grp = blockIdx.x / 9;                   // 0..15 half-slab
    const int dx = tg / 3 - 1, dy = tg % 3 - 1;
    const int x = grp >> 1, yh = (grp & 1) << 2;
    const int sx = (x + dx) & 7;

    // stage shifted tile: local cell lc = ylocal*8 + z, source (sx, yh+ylocal+dy, z)
    #pragma unroll
    for (int k = 0; k < 2; k++) {
        int lc = w * 2 + k;                           // 0..31
        int yl = lc >> 3, z = lc & 7;
        int si = ((sx << 6) | (((yh + yl + dy) & 7) << 3) | z) * 32 + o;
        float v;
        if (stage == 2) {
            float t = __ldg(&g_t[si]);
            v = __ldg(&g_h1[si]) + t * (1.f / (1.f + __expf(-t)));
        } else {
            v = __ldg(&src[si]);
        }
        s_in[lc * 32 + o] = v;
    }
    __syncthreads();

    float acc[2] = {0.f, 0.f};
    #pragma unroll
    for (int t = 0; t < 3; t++) {                     // dz = t-1
        int tap = tg * 3 + t;
        const float* kp = kern + tap * 1024 + o;      // [tap][i][o], lane-coalesced
        float kv[32];
        #pragma unroll
        for (int i = 0; i < 32; i++) kv[i] = __ldg(kp + i * 32);

        #pragma unroll
        for (int k = 0; k < 2; k++) {
            int lc = w * 2 + k;
            int yl = lc >> 3, z = lc & 7;
            int lcs = yl * 8 + ((z + t - 1) & 7);     // z-rotated source cell
            #pragma unroll
            for (int i4 = 0; i4 < 8; i4++) {
                float4 sv = *reinterpret_cast<const float4*>(&s_in[lcs * 32 + i4 * 4]);
                acc[k] += sv.x * kv[i4 * 4 + 0] + sv.y * kv[i4 * 4 + 1]
                        + sv.z * kv[i4 * 4 + 2] + sv.w * kv[i4 * 4 + 3];
            }
        }
    }
    #pragma unroll
    for (int k = 0; k < 2; k++) {
        int lc = w * 2 + k;
        int yl = lc >> 3, z = lc & 7;
        int cell = (x << 6) | ((yh + yl) << 3) | z;
        atomicAdd(&dst[cell * 32 + o], acc[k]);
    }
}

// -------- 2x2x2 periodic box-sum of decoder output --------
__global__ void box_k() {
    int j = blockIdx.x * 256 + threadIdx.x;
    if (j >= NCELL * C) return;
    int o = j & 31, cell = j >> 5;
    int x = cell >> 6, y = (cell >> 3) & 7, z = cell & 7;
    float s = 0.f;
    #pragma unroll
    for (int k = 0; k < 8; k++) {
        int cx = (x + (k >> 2)) & 7;
        int cy = (y + ((k >> 1) & 1)) & 7;
        int cz = (z + (k & 1)) & 7;
        s += g_out[(((cx << 6) | (cy << 3) | cz) << 5) + o];
    }
    g_B[j] = s;
}

// -------- gather: recompute cell from pos; fully coalesced --------
__global__ void gather_k(const float* __restrict__ pos, float* __restrict__ out, int N) {
    int wid  = blockIdx.x * 8 + (threadIdx.x >> 5);
    int lane = threadIdx.x & 31;
    int p0 = wid * 8;
    if (p0 >= N) return;

    float v = 0.f;
    int gi = p0 * 3 + lane;
    if (lane < 24 && gi < N * 3) v = __ldg(pos + gi);

    int k8 = lane & 7;
    float ax = __shfl_sync(0xffffffffu, v, 3 * k8);
    float ay = __shfl_sync(0xffffffffu, v, 3 * k8 + 1);
    float az = __shfl_sync(0xffffffffu, v, 3 * k8 + 2);
    int cell = ((((int)floorf(ax * 8.f)) & 7) << 6)
             | ((((int)floorf(ay * 8.f)) & 7) << 3)
             |  (((int)floorf(az * 8.f)) & 7);

    #pragma unroll
    for (int k = 0; k < 8; k++) {
        int ck = __shfl_sync(0xffffffffu, cell, k);
        float val = g_B[ck * 32 + lane];
        if (p0 + k < N) out[(p0 + k) * 32 + lane] = val;
    }
}

extern "C" void kernel_launch(void* const* d_in, const int* in_sizes, int n_in,
                              void* d_out, int out_size) {
    const float* pos  = (const float*)d_in[0];
    const float* feat = (const float*)d_in[1];
    const float* enc  = (const float*)d_in[2];
    const float* inn  = (const float*)d_in[3];
    const float* dec  = (const float*)d_in[4];
    float* out = (float*)d_out;
    int N = in_sizes[0] / 3;

    zero_k   <<<384, 256>>>(enc, inn, dec);            // idx 0 (zero + kern transpose)
    bin_k    <<<(N + 255) / 256, 256>>>(pos, N);       // idx 1
    scatter_k<<<NCELL, 512>>>(feat);                   // idx 2 (protected)
    conv_k   <<<144, 512>>>(0);                        // idx 3  <-- profiled slot
    conv_k   <<<144, 512>>>(1);                        // idx 4
    conv_k   <<<144, 512>>>(2);                        // idx 5 (silu fused)
    box_k    <<<64, 256>>>();                          // idx 6
    gather_k <<<(N + 63) / 64, 256>>>(pos, out, N);    // idx 7
}

// round 16
// speedup vs baseline: 1.1419x; 1.1419x over previous
#include <cuda_runtime.h>
#include <math.h>

#define NCELL 512
#define C 32
#define NREP 32           // counter replicas per cell (replica = point_idx & 31)
#define CAP32 64          // slots per (cell, replica); mean ~30.5
#define SCAP 1280         // smem record capacity per bin; mean ~977, +9.7 sigma
#define KT_STAGE 27648    // 27*32*32 per conv stage

// -------- static scratch (no cudaMalloc allowed) --------
__device__ int   g_cnt32[NCELL * NREP];
__device__ int4  g_rec32[NCELL * NREP * CAP32];   // {idx, fx, fy, fz}
__device__ float g_img[NCELL * C];
__device__ float g_h1 [NCELL * C];
__device__ float g_t  [NCELL * C];
__device__ float g_out[NCELL * C];
__device__ float g_B  [NCELL * C];
__device__ float g_kt [3 * KT_STAGE];             // transposed kernels [stage][tap][i][o]
__device__ int   g_pad[32];

// -------- zero counters/buffers + transpose conv kernels to [tap][i][o] --------
__global__ void zero_k(const float* __restrict__ enc, const float* __restrict__ inn,
                       const float* __restrict__ dec) {
    int j = blockIdx.x * 256 + threadIdx.x;          // grid 384 -> 98304 threads
    if (j < NCELL * NREP) g_cnt32[j] = 0;
    if (j < NCELL * C) {
        g_img[j] = 0.f; g_h1[j] = 0.f; g_t[j] = 0.f; g_out[j] = 0.f;
    }
    if (j < KT_STAGE) {                               // one element per stage per thread
        int tap = j >> 10, rem = j & 1023;
        int i = rem >> 5, o = rem & 31;
        int src = (tap * 32 + o) * 32 + i;            // original [tap][o][i]
        g_kt[j]                = __ldg(&enc[src]);
        g_kt[KT_STAGE + j]     = __ldg(&inn[src]);
        g_kt[2 * KT_STAGE + j] = __ldg(&dec[src]);
    }
}

// -------- probes: shift bin_k into ncu's profiled slot (idx 3) --------
__global__ void probe_k() {
    if (threadIdx.x == 0) g_pad[0] = 1;
}

// -------- bin points: 2 points/thread at full occupancy (977 CTAs, MLP 2) --------
__global__ void bin_k(const float* __restrict__ pos, int N) {
    int base = blockIdx.x * 512 + threadIdx.x;
    #pragma unroll
    for (int u = 0; u < 2; u++) {
        int p = base + u * 256;
        if (p < N) {
            float sx = pos[3 * p + 0] * 8.f;
            float sy = pos[3 * p + 1] * 8.f;
            float sz = pos[3 * p + 2] * 8.f;
            float bx = floorf(sx), by = floorf(sy), bz = floorf(sz);
            int cell = ((((int)bx) & 7) << 6) | ((((int)by) & 7) << 3) | (((int)bz) & 7);
            int r = p & (NREP - 1);
            int slot = atomicAdd(&g_cnt32[cell * NREP + r], 1);
            if (slot < CAP32) {
                int4 rec;
                rec.x = p;
                rec.y = __float_as_int(sx - bx);
                rec.z = __float_as_int(sy - by);
                rec.w = __float_as_int(sz - bz);
                g_rec32[(cell * NREP + r) * CAP32 + slot] = rec;
            }
        }
    }
}

#define ACC(rc, fc) { \
    float fx = __int_as_float((rc).y), fy = __int_as_float((rc).z), fz = __int_as_float((rc).w); \
    float gx = 1.f - fx, gy = 1.f - fy, gz = 1.f - fz; \
    float w00 = gy * gz, w01 = gy * fz, w10 = fy * gz, w11 = fy * fz; \
    float p0 = gx * (fc), p1 = fx * (fc); \
    a0 += w00 * p0; a1 += w01 * p0; a2 += w10 * p0; a3 += w11 * p0; \
    a4 += w00 * p1; a5 += w01 * p1; a6 += w10 * p1; a7 += w11 * p1; }

// -------- scatter (R13 protected): 1 CTA/bin, 16 warps, padded smem records,
//          guard-free 4-deep feat prefetch, unroll-4 --------
__global__ void __launch_bounds__(512) scatter_k(const float* __restrict__ feat) {
    __shared__ int4  s_rec[SCAP + 64];
    __shared__ int   s_pref[NREP + 1];
    __shared__ float s_all[16][8][32];

    const int b    = blockIdx.x;
    const int w    = threadIdx.x >> 5;               // 0..15
    const int lane = threadIdx.x & 31;

    if (threadIdx.x < 32) {
        int c = g_cnt32[b * NREP + lane];
        if (c > CAP32) c = CAP32;
        int x = c;
        #pragma unroll
        for (int d = 1; d < 32; d <<= 1) {
            int y = __shfl_up_sync(0xffffffffu, x, d);
            if (lane >= d) x += y;
        }
        s_pref[lane + 1] = x;
        if (lane == 0) s_pref[0] = 0;
    }
    __syncthreads();

    #pragma unroll
    for (int r = w; r < NREP; r += 16) {
        int base = s_pref[r];
        int c    = s_pref[r + 1] - base;
        const int4* src = g_rec32 + (b * NREP + r) * CAP32;
        for (int t = lane; t < c; t += 32) {
            int d = base + t;
            if (d < SCAP) s_rec[d] = __ldg(src + t);
        }
    }
    {
        int Tt = s_pref[NREP]; if (Tt > SCAP) Tt = SCAP;
        if (threadIdx.x < 64) s_rec[Tt + threadIdx.x] = make_int4(0, 0, 0, 0);
    }
    __syncthreads();

    int T = s_pref[NREP];
    if (T > SCAP) T = SCAP;

    float a0=0,a1=0,a2=0,a3=0,a4=0,a5=0,a6=0,a7=0;
    float F[4];
    #pragma unroll
    for (int t = 0; t < 4; t++)
        F[t] = __ldg(feat + s_rec[w + t * 16].x * C + lane);

    int k = 0;
    #pragma unroll 4
    for (int j = w; j < T; j += 16, k++) {
        int t = k & 3;
        int4 rc = s_rec[j];
        float fc = F[t];
        F[t] = __ldg(feat + s_rec[j + 64].x * C + lane);
        ACC(rc, fc);
    }

    s_all[w][0][lane] = a0; s_all[w][1][lane] = a1;
    s_all[w][2][lane] = a2; s_all[w][3][lane] = a3;
    s_all[w][4][lane] = a4; s_all[w][5][lane] = a5;
    s_all[w][6][lane] = a6; s_all[w][7][lane] = a7;
    __syncthreads();

    int cn = w & 7;
    int qb = (w >> 3) * 8;
    float s = 0.f;
    #pragma unroll
    for (int q = 0; q < 8; q++) s += s_all[qb + q][cn][lane];
    int bx = b >> 6, by = (b >> 3) & 7, bz = b & 7;
    int cx = (bx + (cn >> 2)) & 7;
    int cy = (by + ((cn >> 1) & 1)) & 7;
    int cz = (bz + (cn & 1)) & 7;
    atomicAdd(&g_img[((cx << 6) | (cy << 3) | cz) * C + lane], s);
}

// -------- periodic 3x3x3 conv (R14 frozen optimum): 27 taps x 16 half-slabs,
//          256 threads, coalesced transposed kernel loads --------
// stage 0: img->h1; stage 1: h1->t; stage 2: decoder with fused h1+silu(t) staging
__global__ void conv_k(int stage) {
    const float* src = (stage == 0) ? g_img : g_h1;
    float*       dst = (stage == 0) ? g_h1  : (stage == 1) ? g_t : g_out;
    const float* kern = g_kt + stage * KT_STAGE;

    __shared__ float s_in[32 * 32];
    const int tid = threadIdx.x;
    const int o = tid & 31, w = tid >> 5;
    const int tap = blockIdx.x % 27;
    const int grp = blockIdx.x / 27;
    const int dx = tap / 9 - 1, dy = (tap / 3) % 3 - 1, dz = tap % 3 - 1;
    const int x = grp >> 1, yh = (grp & 1) << 2;
    const int sx = (x + dx) & 7;

    // coalesced weight loads: kern[tap][i][o], lane = o contiguous (1 wavefront each)
    float kv[32];
    const float* kp = kern + tap * 1024 + o;
    #pragma unroll
    for (int i = 0; i < 32; i++) kv[i] = __ldg(kp + i * 32);

    #pragma unroll
    for (int k = 0; k < 4; k++) {
        int lc = w * 4 + k;
        int y = yh + (lc >> 3), z = lc & 7;
        int si = ((sx << 6) | (((y + dy) & 7) << 3) | ((z + dz) & 7)) * 32 + o;
        float v;
        if (stage == 2) {
            float t = __ldg(&g_t[si]);
            v = __ldg(&g_h1[si]) + t * (1.f / (1.f + __expf(-t)));
        } else {
            v = __ldg(&src[si]);
        }
        s_in[lc * 32 + o] = v;
    }
    __syncthreads();

    float acc[4] = {0,0,0,0};
    #pragma unroll
    for (int i4 = 0; i4 < 8; i4++) {
        #pragma unroll
        for (int k = 0; k < 4; k++) {
            float4 sv = *reinterpret_cast<const float4*>(&s_in[(w * 4 + k) * 32 + i4 * 4]);
            acc[k] += sv.x * kv[i4 * 4 + 0] + sv.y * kv[i4 * 4 + 1]
                    + sv.z * kv[i4 * 4 + 2] + sv.w * kv[i4 * 4 + 3];
        }
    }
    int base = (grp * 32 + w * 4) * 32 + o;
    #pragma unroll
    for (int k = 0; k < 4; k++)
        atomicAdd(&dst[base + k * 32], acc[k]);
}

// -------- 2x2x2 periodic box-sum of decoder output --------
__global__ void box_k() {
    int j = blockIdx.x * 256 + threadIdx.x;
    if (j >= NCELL * C) return;
    int o = j & 31, cell = j >> 5;
    int x = cell >> 6, y = (cell >> 3) & 7, z = cell & 7;
    float s = 0.f;
    #pragma unroll
    for (int k = 0; k < 8; k++) {
        int cx = (x + (k >> 2)) & 7;
        int cy = (y + ((k >> 1) & 1)) & 7;
        int cz = (z + (k & 1)) & 7;
        s += g_out[(((cx << 6) | (cy << 3) | cz) << 5) + o];
    }
    g_B[j] = s;
}

// -------- gather: recompute cell from pos; fully coalesced --------
__global__ void gather_k(const float* __restrict__ pos, float* __restrict__ out, int N) {
    int wid  = blockIdx.x * 8 + (threadIdx.x >> 5);
    int lane = threadIdx.x & 31;
    int p0 = wid * 8;
    if (p0 >= N) return;

    float v = 0.f;
    int gi = p0 * 3 + lane;
    if (lane < 24 && gi < N * 3) v = __ldg(pos + gi);

    int k8 = lane & 7;
    float ax = __shfl_sync(0xffffffffu, v, 3 * k8);
    float ay = __shfl_sync(0xffffffffu, v, 3 * k8 + 1);
    float az = __shfl_sync(0xffffffffu, v, 3 * k8 + 2);
    int cell = ((((int)floorf(ax * 8.f)) & 7) << 6)
             | ((((int)floorf(ay * 8.f)) & 7) << 3)
             |  (((int)floorf(az * 8.f)) & 7);

    #pragma unroll
    for (int k = 0; k < 8; k++) {
        int ck = __shfl_sync(0xffffffffu, cell, k);
        float val = g_B[ck * 32 + lane];
        if (p0 + k < N) out[(p0 + k) * 32 + lane] = val;
    }
}

extern "C" void kernel_launch(void* const* d_in, const int* in_sizes, int n_in,
                              void* d_out, int out_size) {
    const float* pos  = (const float*)d_in[0];
    const float* feat = (const float*)d_in[1];
    const float* enc  = (const float*)d_in[2];
    const float* inn  = (const float*)d_in[3];
    const float* dec  = (const float*)d_in[4];
    float* out = (float*)d_out;
    int N = in_sizes[0] / 3;

    zero_k   <<<384, 256>>>(enc, inn, dec);            // idx 0 (zero + kern transpose)
    probe_k  <<<1, 32>>>();                            // idx 1
    probe_k  <<<1, 32>>>();                            // idx 2
    bin_k    <<<(N + 511) / 512, 256>>>(pos, N);       // idx 3  <-- profiled slot
    scatter_k<<<NCELL, 512>>>(feat);                   // idx 4 (protected)
    conv_k   <<<432, 256>>>(0);                        // idx 5 (R14 frozen)
    conv_k   <<<432, 256>>>(1);                        // idx 6
    conv_k   <<<432, 256>>>(2);                        // idx 7 (silu fused)
    box_k    <<<64, 256>>>();                          // idx 8
    gather_k <<<(N + 63) / 64, 256>>>(pos, out, N);    // idx 9
}

// round 17
// speedup vs baseline: 1.2036x; 1.0541x over previous
#include <cuda_runtime.h>
#include <math.h>

#define NCELL 512
#define C 32
#define NREP 32           // counter replicas per cell (replica = point_idx & 31)
#define CAP32 64          // slots per (cell, replica); mean ~30.5
#define SCAP 1280         // smem record capacity per bin; mean ~977, +9.7 sigma
#define KT_STAGE 27648    // 27*32*32 per conv stage

// -------- static scratch (no cudaMalloc allowed) --------
__device__ int   g_cnt32[NCELL * NREP];
__device__ int4  g_rec32[NCELL * NREP * CAP32];   // {idx, fx, fy, fz}
__device__ float g_img[NCELL * C];
__device__ float g_h1 [NCELL * C];
__device__ float g_t  [NCELL * C];
__device__ float g_out[NCELL * C];
__device__ float g_B  [NCELL * C];
__device__ float g_kt [3 * KT_STAGE];             // transposed kernels [stage][tap][i][o]

// -------- zero counters/buffers + transpose conv kernels to [tap][i][o] --------
__global__ void zero_k(const float* __restrict__ enc, const float* __restrict__ inn,
                       const float* __restrict__ dec) {
    int j = blockIdx.x * 256 + threadIdx.x;          // grid 384 -> 98304 threads
    if (j < NCELL * NREP) g_cnt32[j] = 0;
    if (j < NCELL * C) {
        g_img[j] = 0.f; g_h1[j] = 0.f; g_t[j] = 0.f; g_out[j] = 0.f;
    }
    if (j < KT_STAGE) {                               // one element per stage per thread
        int tap = j >> 10, rem = j & 1023;
        int i = rem >> 5, o = rem & 31;
        int src = (tap * 32 + o) * 32 + i;            // original [tap][o][i]
        g_kt[j]                = __ldg(&enc[src]);
        g_kt[KT_STAGE + j]     = __ldg(&inn[src]);
        g_kt[2 * KT_STAGE + j] = __ldg(&dec[src]);
    }
}

// -------- bin points (R8 measured-best config: 1 point/thread; ~13.5us floor) --------
__global__ void bin_k(const float* __restrict__ pos, int N) {
    int p = blockIdx.x * 256 + threadIdx.x;
    if (p >= N) return;
    float sx = pos[3 * p + 0] * 8.f;
    float sy = pos[3 * p + 1] * 8.f;
    float sz = pos[3 * p + 2] * 8.f;
    float bx = floorf(sx), by = floorf(sy), bz = floorf(sz);
    int cell = ((((int)bx) & 7) << 6) | ((((int)by) & 7) << 3) | (((int)bz) & 7);
    int r = p & (NREP - 1);
    int slot = atomicAdd(&g_cnt32[cell * NREP + r], 1);
    if (slot < CAP32) {
        int4 rec;
        rec.x = p;
        rec.y = __float_as_int(sx - bx);
        rec.z = __float_as_int(sy - by);
        rec.w = __float_as_int(sz - bz);
        g_rec32[(cell * NREP + r) * CAP32 + slot] = rec;
    }
}

#define ACC(rc, fc) { \
    float fx = __int_as_float((rc).y), fy = __int_as_float((rc).z), fz = __int_as_float((rc).w); \
    float gx = 1.f - fx, gy = 1.f - fy, gz = 1.f - fz; \
    float w00 = gy * gz, w01 = gy * fz, w10 = fy * gz, w11 = fy * fz; \
    float p0 = gx * (fc), p1 = fx * (fc); \
    a0 += w00 * p0; a1 += w01 * p0; a2 += w10 * p0; a3 += w11 * p0; \
    a4 += w00 * p1; a5 += w01 * p1; a6 += w10 * p1; a7 += w11 * p1; }

// -------- scatter (R13 protected): 1 CTA/bin, 16 warps, padded smem records,
//          guard-free 4-deep feat prefetch, unroll-4 --------
__global__ void __launch_bounds__(512) scatter_k(const float* __restrict__ feat) {
    __shared__ int4  s_rec[SCAP + 64];
    __shared__ int   s_pref[NREP + 1];
    __shared__ float s_all[16][8][32];

    const int b    = blockIdx.x;
    const int w    = threadIdx.x >> 5;               // 0..15
    const int lane = threadIdx.x & 31;

    if (threadIdx.x < 32) {
        int c = g_cnt32[b * NREP + lane];
        if (c > CAP32) c = CAP32;
        int x = c;
        #pragma unroll
        for (int d = 1; d < 32; d <<= 1) {
            int y = __shfl_up_sync(0xffffffffu, x, d);
            if (lane >= d) x += y;
        }
        s_pref[lane + 1] = x;
        if (lane == 0) s_pref[0] = 0;
    }
    __syncthreads();

    #pragma unroll
    for (int r = w; r < NREP; r += 16) {
        int base = s_pref[r];
        int c    = s_pref[r + 1] - base;
        const int4* src = g_rec32 + (b * NREP + r) * CAP32;
        for (int t = lane; t < c; t += 32) {
            int d = base + t;
            if (d < SCAP) s_rec[d] = __ldg(src + t);
        }
    }
    {
        int Tt = s_pref[NREP]; if (Tt > SCAP) Tt = SCAP;
        if (threadIdx.x < 64) s_rec[Tt + threadIdx.x] = make_int4(0, 0, 0, 0);
    }
    __syncthreads();

    int T = s_pref[NREP];
    if (T > SCAP) T = SCAP;

    float a0=0,a1=0,a2=0,a3=0,a4=0,a5=0,a6=0,a7=0;
    float F[4];
    #pragma unroll
    for (int t = 0; t < 4; t++)
        F[t] = __ldg(feat + s_rec[w + t * 16].x * C + lane);

    int k = 0;
    #pragma unroll 4
    for (int j = w; j < T; j += 16, k++) {
        int t = k & 3;
        int4 rc = s_rec[j];
        float fc = F[t];
        F[t] = __ldg(feat + s_rec[j + 64].x * C + lane);
        ACC(rc, fc);
    }

    s_all[w][0][lane] = a0; s_all[w][1][lane] = a1;
    s_all[w][2][lane] = a2; s_all[w][3][lane] = a3;
    s_all[w][4][lane] = a4; s_all[w][5][lane] = a5;
    s_all[w][6][lane] = a6; s_all[w][7][lane] = a7;
    __syncthreads();

    int cn = w & 7;
    int qb = (w >> 3) * 8;
    float s = 0.f;
    #pragma unroll
    for (int q = 0; q < 8; q++) s += s_all[qb + q][cn][lane];
    int bx = b >> 6, by = (b >> 3) & 7, bz = b & 7;
    int cx = (bx + (cn >> 2)) & 7;
    int cy = (by + ((cn >> 1) & 1)) & 7;
    int cz = (bz + (cn & 1)) & 7;
    atomicAdd(&g_img[((cx << 6) | (cy << 3) | cz) * C + lane], s);
}

// -------- periodic 3x3x3 conv: 27 taps x 32 groups (8 cells/CTA), coalesced
//          transposed kernel loads. Split is viable now that weight loads are
//          1 wavefront each (R12's blocker removed by the R14 transpose). --------
// stage 0: img->h1; stage 1: h1->t; stage 2: decoder with fused h1+silu(t) staging
__global__ void conv_k(int stage) {
    const float* src = (stage == 0) ? g_img : g_h1;
    float*       dst = (stage == 0) ? g_h1  : (stage == 1) ? g_t : g_out;
    const float* kern = g_kt + stage * KT_STAGE;

    __shared__ float s_in[8 * 32];
    const int tid = threadIdx.x;
    const int o = tid & 31, w = tid >> 5;
    const int tap = blockIdx.x % 27;
    const int grp = blockIdx.x / 27;                  // 0..31: x(3b) | yq(2b)
    const int dx = tap / 9 - 1, dy = (tap / 3) % 3 - 1, dz = tap % 3 - 1;
    const int x = grp >> 2, yq = (grp & 3) << 1;      // 2 y-rows, 8 z -> wait 8 cells: 1 y-row? 
    // 8 cells per CTA: one (x, y) row of 8 z-cells... grp = x(3b)|y(3b) -> 64 groups? Use 32 groups of 2 rows /4 cells?
    // Simpler: 8 cells = y row pair? Keep: grp in 0..63 would be 1728 CTAs. Use 864 CTAs: 32 groups x 16 cells? No.
    // 864 = 27*32: 32 groups, 16 cells each (matches R12 geometry).
    const int yh = (grp & 3) << 1;                    // 2 y-rows per group (16 cells)
    const int sx = (x + dx) & 7;

    // coalesced weight loads: kern[tap][i][o], lane = o contiguous (1 wavefront each)
    float kv[32];
    const float* kp = kern + tap * 1024 + o;
    #pragma unroll
    for (int i = 0; i < 32; i++) kv[i] = __ldg(kp + i * 32);

    __shared__ float s_in16[16 * 32];
    #pragma unroll
    for (int k = 0; k < 2; k++) {
        int lc = w * 2 + k;                           // 0..15 local cell
        int y = yh + (lc >> 3), z = lc & 7;
        int si = ((sx << 6) | (((y + dy) & 7) << 3) | ((z + dz) & 7)) * 32 + o;
        float v;
        if (stage == 2) {
            float t = __ldg(&g_t[si]);
            v = __ldg(&g_h1[si]) + t * (1.f / (1.f + __expf(-t)));
        } else {
            v = __ldg(&src[si]);
        }
        s_in16[lc * 32 + o] = v;
    }
    __syncthreads();

    float acc[2] = {0.f, 0.f};
    #pragma unroll
    for (int i4 = 0; i4 < 8; i4++) {
        #pragma unroll
        for (int k = 0; k < 2; k++) {
            float4 sv = *reinterpret_cast<const float4*>(&s_in16[(w * 2 + k) * 32 + i4 * 4]);
            acc[k] += sv.x * kv[i4 * 4 + 0] + sv.y * kv[i4 * 4 + 1]
                    + sv.z * kv[i4 * 4 + 2] + sv.w * kv[i4 * 4 + 3];
        }
    }
    #pragma unroll
    for (int k = 0; k < 2; k++) {
        int lc = w * 2 + k;
        int y = yh + (lc >> 3), z = lc & 7;
        int cell = (x << 6) | (y << 3) | z;
        atomicAdd(&dst[cell * 32 + o], acc[k]);
    }
    (void)s_in;
}

// -------- 2x2x2 periodic box-sum of decoder output --------
__global__ void box_k() {
    int j = blockIdx.x * 256 + threadIdx.x;
    if (j >= NCELL * C) return;
    int o = j & 31, cell = j >> 5;
    int x = cell >> 6, y = (cell >> 3) & 7, z = cell & 7;
    float s = 0.f;
    #pragma unroll
    for (int k = 0; k < 8; k++) {
        int cx = (x + (k >> 2)) & 7;
        int cy = (y + ((k >> 1) & 1)) & 7;
        int cz = (z + (k & 1)) & 7;
        s += g_out[(((cx << 6) | (cy << 3) | cz) << 5) + o];
    }
    g_B[j] = s;
}

// -------- gather: recompute cell from pos; fully coalesced --------
__global__ void gather_k(const float* __restrict__ pos, float* __restrict__ out, int N) {
    int wid  = blockIdx.x * 8 + (threadIdx.x >> 5);
    int lane = threadIdx.x & 31;
    int p0 = wid * 8;
    if (p0 >= N) return;

    float v = 0.f;
    int gi = p0 * 3 + lane;
    if (lane < 24 && gi < N * 3) v = __ldg(pos + gi);

    int k8 = lane & 7;
    float ax = __shfl_sync(0xffffffffu, v, 3 * k8);
    float ay = __shfl_sync(0xffffffffu, v, 3 * k8 + 1);
    float az = __shfl_sync(0xffffffffu, v, 3 * k8 + 2);
    int cell = ((((int)floorf(ax * 8.f)) & 7) << 6)
             | ((((int)floorf(ay * 8.f)) & 7) << 3)
             |  (((int)floorf(az * 8.f)) & 7);

    #pragma unroll
    for (int k = 0; k < 8; k++) {
        int ck = __shfl_sync(0xffffffffu, cell, k);
        float val = g_B[ck * 32 + lane];
        if (p0 + k < N) out[(p0 + k) * 32 + lane] = val;
    }
}

extern "C" void kernel_launch(void* const* d_in, const int* in_sizes, int n_in,
                              void* d_out, int out_size) {
    const float* pos  = (const float*)d_in[0];
    const float* feat = (const float*)d_in[1];
    const float* enc  = (const float*)d_in[2];
    const float* inn  = (const float*)d_in[3];
    const float* dec  = (const float*)d_in[4];
    float* out = (float*)d_out;
    int N = in_sizes[0] / 3;

    zero_k   <<<384, 256>>>(enc, inn, dec);            // idx 0 (zero + kern transpose)
    bin_k    <<<(N + 255) / 256, 256>>>(pos, N);       // idx 1
    scatter_k<<<NCELL, 512>>>(feat);                   // idx 2 (protected)
    conv_k   <<<864, 256>>>(0);                        // idx 3  <-- profiled slot
    conv_k   <<<864, 256>>>(1);                        // idx 4
    conv_k   <<<864, 256>>>(2);                        // idx 5 (silu fused)
    box_k    <<<64, 256>>>();                          // idx 6
    gather_k <<<(N + 63) / 64, 256>>>(pos, out, N);    // idx 7
}